// round 16
// baseline (speedup 1.0000x reference)
#include <cuda_runtime.h>

#define NB 4096
#define NF 1024
#define NR 64
#define NK 32
#define ND 16
#define THREADS 256
#define LOG_2PI 1.8378770664093453f

typedef unsigned long long ull;

// Per-(r,k,d) coefficients {inv0,nmi0,inv1,nmi1}, layout [r][d/2][k]:
// lane k loads one float4 per 2 d's (coalesced LDG.128, 8 per region).
__device__ float4 g_coef4[NR * (ND / 2) * NK];
__device__ float g_c[NR * NK];          // -(sum log s) - 0.5*D*log(2pi)
__device__ int g_idxb[NR * ND];         // region col -> byte offset c*16
// Transposed x: quad q (rows 4q..4q+3), column c -> float4 at [q*NF + c].
// Plane stride per quad = NF*16 = 16384 B. 16 MB, L2-resident.
__device__ float4 g_xt[(NB / 4) * NF];

__global__ void prep_kernel(const float* __restrict__ means,
                            const float* __restrict__ scales) {
    int id = blockIdx.x * blockDim.x + threadIdx.x;  // r*NK + k
    if (id >= NR * NK) return;
    int r = id / NK, k = id % NK;
    const float* m = means + (size_t)id * ND;
    const float* s = scales + (size_t)id * ND;
    float logdet = 0.f;
#pragma unroll
    for (int d2 = 0; d2 < ND / 2; d2++) {
        float s0 = s[2 * d2], s1 = s[2 * d2 + 1];
        float i0 = 1.0f / s0, i1 = 1.0f / s1;
        float4 c;
        c.x = i0; c.y = -m[2 * d2] * i0;
        c.z = i1; c.w = -m[2 * d2 + 1] * i1;
        g_coef4[(r * (ND / 2) + d2) * NK + k] = c;
        logdet += logf(s0) + logf(s1);
    }
    g_c[id] = -logdet - 0.5f * ND * LOG_2PI;
}

// Normalize region indices (int64 or int32, sniffed) to byte offsets c*16.
__global__ void idx_kernel(const int* __restrict__ regions32) {
    __shared__ int s_nz;
    int tid = threadIdx.x;
    if (tid == 0) s_nz = 0;
    __syncthreads();
    // int64 little-endian with values <1024 -> all odd words zero.
    int nz = regions32[2 * tid + 1] | regions32[2 * (tid + 256) + 1];
    if (nz) atomicOr(&s_nz, 1);
    __syncthreads();
    int is32 = s_nz;
    for (int i = tid; i < NR * ND; i += 256) {
        int v = is32 ? regions32[i] : regions32[2 * i];
        g_idxb[i] = (v & (NF - 1)) << 4;   // c * 16 bytes
    }
}

// x[4096][1024] -> g_xt[q][c] = {x[4q][c], x[4q+1][c], x[4q+2][c], x[4q+3][c]}
// Warp reads 4x coalesced 128B rows, writes 512B coalesced.
__global__ void transpose_kernel(const float* __restrict__ x) {
    int t = blockIdx.x * blockDim.x + threadIdx.x;   // 0 .. NB/4*NF-1
    int c = t & (NF - 1);
    int q = t >> 10;
    const float* xp = x + (size_t)(4 * q) * NF + c;
    float4 v;
    v.x = xp[0 * NF];
    v.y = xp[1 * NF];
    v.z = xp[2 * NF];
    v.w = xp[3 * NF];
    g_xt[(size_t)q * NF + c] = v;
}

// -------- packed f32x2 helpers (FFMA2 path: PTX-only on sm_103a) --------
__device__ __forceinline__ ull pk2(float v) {          // {v, v}
    ull r; asm("mov.b64 %0, {%1, %1};" : "=l"(r) : "f"(v)); return r;
}
__device__ __forceinline__ ull fma2(ull a, ull b, ull c) {
    ull d; asm("fma.rn.f32x2 %0, %1, %2, %3;" : "=l"(d) : "l"(a), "l"(b), "l"(c));
    return d;
}
__device__ __forceinline__ void unpk2(ull v, float& lo, float& hi) {
    asm("mov.b64 {%0, %1}, %2;" : "=f"(lo), "=f"(hi) : "l"(v));
}

// Task = one warp x one region x 16 rows. Lane = k. No shared memory:
// x comes via lane-uniform LDG.128 quads from g_xt (1 line -> 1 wavefront).
__global__ void __launch_bounds__(THREADS, 3) gauss_kernel(
        float* __restrict__ out) {
    int gw = (blockIdx.x * THREADS + threadIdx.x) >> 5;  // 0..16383
    int l = threadIdx.x & 31;                            // lane == k
    int rg = gw >> 6;                                    // rowgroup 0..255
    int r = gw & (NR - 1);                               // region
    int b0 = rg * 16;

    const char* base = (const char*)g_xt + (size_t)rg * 4 * (NF * 16);
    const int4* rp4 = (const int4*)(g_idxb + r * ND);
    const float4* cg = g_coef4 + r * (ND / 2) * NK + l;
    float C = g_c[r * NK + l];

    ull acc[8];                                          // acc[j]: rows 2j,2j+1
#pragma unroll
    for (int j = 0; j < 8; j++) acc[j] = 0;

#pragma unroll
    for (int q = 0; q < 4; q++) {            // q covers d = 4q .. 4q+3
        int4 P = rp4[q];                     // uniform LDG.128 (byte offs c*16)
        float4 c0 = cg[(2 * q) * NK];        // coefs d = 4q, 4q+1
        float4 c1 = cg[(2 * q + 1) * NK];    // coefs d = 4q+2, 4q+3
        ull i0 = pk2(c0.x), n0 = pk2(c0.y);
        ull i1 = pk2(c0.z), n1 = pk2(c0.w);
        ull i2 = pk2(c1.x), n2 = pk2(c1.y);
        ull i3 = pk2(c1.z), n3 = pk2(c1.w);
        const char* a0 = base + P.x;         // uniform addresses; quad plane
        const char* a1 = base + P.y;         // stride 16384 is an immediate
        const char* a2 = base + P.z;
        const char* a3 = base + P.w;
#pragma unroll
        for (int i = 0; i < 4; i++) {        // quad i = rows 4i..4i+3
            ull z;
            ulonglong2 X0 = *(const ulonglong2*)(a0 + i * 16384);
            z = fma2(X0.x, i0, n0); acc[2 * i]     = fma2(z, z, acc[2 * i]);
            z = fma2(X0.y, i0, n0); acc[2 * i + 1] = fma2(z, z, acc[2 * i + 1]);
            ulonglong2 X1 = *(const ulonglong2*)(a1 + i * 16384);
            z = fma2(X1.x, i1, n1); acc[2 * i]     = fma2(z, z, acc[2 * i]);
            z = fma2(X1.y, i1, n1); acc[2 * i + 1] = fma2(z, z, acc[2 * i + 1]);
            ulonglong2 X2 = *(const ulonglong2*)(a2 + i * 16384);
            z = fma2(X2.x, i2, n2); acc[2 * i]     = fma2(z, z, acc[2 * i]);
            z = fma2(X2.y, i2, n2); acc[2 * i + 1] = fma2(z, z, acc[2 * i + 1]);
            ulonglong2 X3 = *(const ulonglong2*)(a3 + i * 16384);
            z = fma2(X3.x, i3, n3); acc[2 * i]     = fma2(z, z, acc[2 * i]);
            z = fma2(X3.y, i3, n3); acc[2 * i + 1] = fma2(z, z, acc[2 * i + 1]);
        }
    }

    // out[b][r][k]: lanes contiguous in k -> coalesced 128B stores.
    size_t ob = ((size_t)b0 * NR + r) * NK + l;
    const size_t rs = (size_t)NR * NK;                   // row stride
#pragma unroll
    for (int j = 0; j < 8; j++) {
        float s0, s1;
        unpk2(acc[j], s0, s1);
        out[ob + (size_t)(2 * j) * rs]     = fmaf(s0, -0.5f, C);
        out[ob + (size_t)(2 * j + 1) * rs] = fmaf(s1, -0.5f, C);
    }
}

extern "C" void kernel_launch(void* const* d_in, const int* in_sizes, int n_in,
                              void* d_out, int out_size) {
    const float* x       = (const float*)d_in[0];
    const int* regions   = (const int*)d_in[1];   // int32 or int64, sniffed
    const float* means   = (const float*)d_in[2];
    const float* scales  = (const float*)d_in[3];
    float* out = (float*)d_out;

    prep_kernel<<<(NR * NK + THREADS - 1) / THREADS, THREADS>>>(means, scales);
    idx_kernel<<<1, 256>>>(regions);
    transpose_kernel<<<(NB / 4) * NF / THREADS, THREADS>>>(x);

    // 16384 warp-tasks (256 rowgroups x 64 regions), 8 warps/block.
    gauss_kernel<<<16384 / 8, THREADS>>>(out);
}